// round 16
// baseline (speedup 1.0000x reference)
#include <cuda_runtime.h>
#include <cstdint>

#define N 8400
#define WORDS 132          // ceil(8400/64)
#define SCORE_THR 0.5f
#define IOU_THR 0.5f
#define GRID 136           // <= 148 SMs: all blocks co-resident (wave 1)
#define NT 1024
#define JS 32              // rank j-split
#define NPAD 8448

typedef unsigned long long u64;

struct __align__(16) SpEnt { u64 bits; u64 idx; };

// ---- persistent device state (allocation-free rule) ----
__device__ int g_vcount = 0;
__device__ int g_bar_arrive = 0;
__device__ volatile int g_bar_release = 0;
__device__ int g_bar_exit = 0;
__device__ u64 g_vkey[N];
__device__ float4 g_vbox[N];
__device__ float g_vscore[N];
__device__ int g_rankp[JS][N];
__device__ float4 g_sbox[N];
__device__ float g_sscore[N];
__device__ u64 g_diag2[NPAD][2];           // dense near-diag: own word, next word
__device__ unsigned g_scount[NPAD];        // # sparse entries (wg >= own+2)
__device__ SpEnt g_slist[N][WORDS];        // sparse far-off-diag words (CSR)
__device__ u64 g_rbuf[2][WORDS + 2];       // fixpoint ping-pong (zero at entry)
__device__ int g_diff[2];                  // convergence flags (zero at entry)

// Software grid barrier (all CTAs co-resident since GRID < #SMs).
__device__ __forceinline__ void gbar(int gen) {
    __syncthreads();
    if (threadIdx.x == 0) {
        __threadfence();
        int prev = atomicAdd(&g_bar_arrive, 1);
        if (prev == gen * GRID - 1) {
            g_bar_release = gen;
        } else {
            while (g_bar_release < gen) { __nanosleep(64); }
        }
        __threadfence();
    }
    __syncthreads();
}

__global__ __launch_bounds__(NT) void k_all(const float* __restrict__ in,
                                            float* __restrict__ out) {
    extern __shared__ __align__(16) char dyn[];   // 12,288B phase scratch
    __shared__ u64 sacc[WORDS + 2];
    int tid = threadIdx.x;
    int bid = blockIdx.x;
    int gtid = bid * NT + tid;
    int gen = 0;

    // ---------------- Phase 1: decode + compact valid ----------------------
    {
        int a = gtid;
        int lane = tid & 31;
        bool valid = false;
        float4 b = make_float4(0.f, 0.f, 0.f, 0.f);
        float s = 0.f;
        u64 key = 0ull;
        if (a < N) {
            float cx = in[a];
            float cy = in[N + a];
            float w  = in[2 * N + a];
            float h  = in[3 * N + a];
            s = in[4 * N + a];
            float hw = __fmul_rn(w, 0.5f);
            float hh = __fmul_rn(h, 0.5f);
            b.x = __fsub_rn(cx, hw);
            b.y = __fsub_rn(cy, hh);
            b.z = __fadd_rn(cx, hw);
            b.w = __fadd_rn(cy, hh);
            valid = (s >= SCORE_THR);
            key = (((u64)__float_as_uint(s)) << 14) | (u64)(16383 - a);
            g_scount[a] = 0u;
            g_diag2[a][0] = 0ull;
            g_diag2[a][1] = 0ull;
        }
        unsigned m = __ballot_sync(0xffffffffu, valid);
        if (m != 0u) {
            int leader = __ffs(m) - 1;
            int base = 0;
            if (lane == leader) base = atomicAdd(&g_vcount, __popc(m));
            base = __shfl_sync(0xffffffffu, base, leader);
            if (valid) {
                int pos = base + __popc(m & ((1u << lane) - 1u));
                g_vkey[pos]   = key;
                g_vbox[pos]   = b;
                g_vscore[pos] = s;
            }
        }
    }
    gbar(++gen);
    int V = *(volatile int*)&g_vcount;
    int T = (V + 63) >> 6;

    // ---------------- Phase 2: rank partials (i-blocks x 32 j-chunks) ------
    {
        u64* sk = (u64*)dyn;
        int IB = (V + NT - 1) / NT;
        int CH = (V + JS - 1) / JS;
        int ntasks = IB * JS;
        for (int task = bid; task < ntasks; task += GRID) {
            int ib = task % IB;
            int jb = task / IB;
            int jlo = jb * CH;
            int mlen = min(jlo + CH, V) - jlo;
            __syncthreads();
            for (int d = tid; d < mlen; d += NT)
                sk[d] = g_vkey[jlo + d];
            __syncthreads();
            int p = ib * NT + tid;
            u64 kp = (p < V) ? g_vkey[p] : 0ull;
            int cnt = 0;
#pragma unroll 8
            for (int d = 0; d < mlen; ++d)
                cnt += (sk[d] > kp) ? 1 : 0;
            if (p < V) g_rankp[jb][p] = cnt;
        }
    }
    gbar(++gen);

    // ---------------- Phase 3: sum partials + scatter -----------------------
    for (int p = gtid; p < V; p += GRID * NT) {
        int r = 0;
#pragma unroll
        for (int y = 0; y < JS; ++y) r += g_rankp[y][p];
        g_sbox[r]   = g_vbox[p];
        g_sscore[r] = g_vscore[p];
    }
    gbar(++gen);

    // ---------------- Phase 4: IoU -> diag2 + CSR far entries --------------
    {
        int h  = tid >> 9;                         // half-block tasks
        int ht = tid & 511;
        float4* cbox  = (float4*)(dyn + h * 5120);
        float*  carea = (float*)(dyn + h * 5120 + 4096);
        int TvR = (V + 127) >> 7;
        int TvC = (V + 255) >> 8;
        int ntasks = 0;
        for (int rb = 0; rb < TvR; ++rb) ntasks += TvC - (rb >> 1);
        int rounds = (ntasks + 2 * GRID - 1) / (2 * GRID);
        for (int rd = 0; rd < rounds; ++rd) {
            int task = rd * 2 * GRID + bid * 2 + h;
            bool live = (task < ntasks);
            int rb = 0, cB = 0;
            if (live) {
                int rem = task;
                while (rem >= TvC - (rb >> 1)) { rem -= TvC - (rb >> 1); rb++; }
                cB = (rb >> 1) + rem;
            }
            __syncthreads();
            if (live && ht < 256) {
                int j = cB * 256 + ht;
                if (j < V) {
                    float4 b = g_sbox[j];
                    cbox[ht] = b;
                    carea[ht] = __fmul_rn(__fsub_rn(b.z, b.x),
                                          __fsub_rn(b.w, b.y));
                } else {
                    cbox[ht] = make_float4(0.f, 0.f, 0.f, 0.f);
                    carea[ht] = 0.f;
                }
            }
            __syncthreads();
            if (live) {
                int row = ht & 127;
                int wq  = ht >> 7;
                int i = rb * 128 + row;
                int wg = cB * 4 + wq;
                int dstart = max(0, i + 1 - wg * 64);
                if (i < V && dstart < 64) {
                    float4 bi = g_sbox[i];
                    float ai = __fmul_rn(__fsub_rn(bi.z, bi.x),
                                         __fsub_rn(bi.w, bi.y));
                    int cbase = wq * 64;
                    u64 bits = 0ull;
                    for (int d = dstart; d < 64; ++d) {
                        float4 bj = cbox[cbase + d];
                        float ltx = fmaxf(bi.x, bj.x);
                        float lty = fmaxf(bi.y, bj.y);
                        float rbx = fminf(bi.z, bj.z);
                        float rby = fminf(bi.w, bj.w);
                        float wx = fmaxf(__fsub_rn(rbx, ltx), 0.0f);
                        float wy = fmaxf(__fsub_rn(rby, lty), 0.0f);
                        float inter = __fmul_rn(wx, wy);
                        float uni = __fsub_rn(__fadd_rn(ai, carea[cbase + d]),
                                              inter);
                        float den = fmaxf(uni, 1e-9f);
                        float halfd = __fmul_rn(0.5f, den);
                        bool hit = false;
                        if (inter > halfd) {
                            if (inter > __fmul_rn(0.5005f, den)) hit = true;
                            else hit = (__fdiv_rn(inter, den) > IOU_THR);
                        }
                        if (hit) bits |= (1ull << d);
                    }
                    int own = i >> 6;
                    if (wg == own) {
                        g_diag2[i][0] = bits;
                    } else if (wg == own + 1) {
                        g_diag2[i][1] = bits;
                    } else if (bits) {
                        unsigned pos = atomicAdd(&g_scount[i], 1u);
                        SpEnt e; e.bits = bits; e.idx = (u64)wg;
                        g_slist[i][pos] = e;
                    }
                }
            }
        }
    }
    gbar(++gen);

    // ---------------- Phase 5: parallel fixed-point NMS --------------------
    // r^{k+1}[i] = OR_{j<i, !r^k[j]} M[j][i]; unique fixpoint = greedy keep.
    // Converges once all suppression chains of depth <= k are resolved.
    int fin = 0;
    for (int k = 0; ; ++k) {
        int cur = k & 1;
        u64* rc = g_rbuf[cur];          // r^k   (complete)
        u64* rn = g_rbuf[cur ^ 1];      // r^{k+1} (pre-zeroed)
        // --- accumulate: 8 threads per row; block-local SMEM then REDG
        for (int w = tid; w < T + 2; w += NT) sacc[w] = 0ull;
        if (gtid == 0) g_diff[cur] = 0;
        __syncthreads();
        {
            int row = gtid >> 3;
            int sub = gtid & 7;
            if (row < V) {
                bool kept = !((rc[row >> 6] >> (row & 63)) & 1ull);
                if (kept) {
                    if (sub == 0) {
                        u64 d0 = g_diag2[row][0];
                        u64 d1 = g_diag2[row][1];
                        int own = row >> 6;
                        if (d0) atomicOr(&sacc[own], d0);
                        if (d1) atomicOr(&sacc[own + 1], d1);
                    }
                    int cnt = (int)g_scount[row];
                    const SpEnt* lp = &g_slist[row][0];
                    for (int e = sub; e < cnt; e += 8) {
                        ulonglong2 ent = *(const ulonglong2*)&lp[e];  // LDG.128
                        atomicOr(&sacc[(int)ent.y], ent.x);
                    }
                }
            }
        }
        __syncthreads();
        for (int w = tid; w < T + 2; w += NT)
            if (sacc[w]) atomicOr(&rn[w], sacc[w]);
        gbar(++gen);
        // --- compare r^{k+1} vs r^k; zero r^k (target of iteration k+2)
        bool mydiff = false;
        for (int w = gtid; w < T + 2; w += GRID * NT) {
            u64 a = rc[w], b = rn[w];
            if (a != b) mydiff = true;
            rc[w] = 0ull;
        }
        if (mydiff) g_diff[cur] = 1;
        gbar(++gen);
        if (*(volatile int*)&g_diff[cur] == 0) { fin = cur ^ 1; break; }
    }

    // ---------------- Output (grid-parallel) -------------------------------
    {
        u64* rf = g_rbuf[fin];
        for (int p = gtid; p < N; p += GRID * NT) {
            bool kept = (p < V) && !((rf[p >> 6] >> (p & 63)) & 1ull);
            float4 b = kept ? g_sbox[p] : make_float4(0.f, 0.f, 0.f, 0.f);
            float s = kept ? g_sscore[p] : 0.f;
            out[p * 5 + 0] = b.x;
            out[p * 5 + 1] = b.y;
            out[p * 5 + 2] = b.z;
            out[p * 5 + 3] = b.w;
            out[p * 5 + 4] = s;
        }
    }
    gbar(++gen);

    // ---------------- Cleanup for next graph replay ------------------------
    for (int w = gtid; w < T + 2; w += GRID * NT) g_rbuf[fin][w] = 0ull;
    if (gtid == 0) { g_diff[0] = 0; g_diff[1] = 0; }

    __syncthreads();
    if (bid != 0) {
        if (tid == 0) atomicAdd(&g_bar_exit, 1);
        return;
    }
    if (tid == 0) {
        while (*(volatile int*)&g_bar_exit < GRID - 1) { __nanosleep(64); }
        g_bar_exit = 0;
        g_bar_arrive = 0;
        g_bar_release = 0;
        g_vcount = 0;
        __threadfence();
    }
}

extern "C" void kernel_launch(void* const* d_in, const int* in_sizes, int n_in,
                              void* d_out, int out_size) {
    const float* in = (const float*)d_in[0];
    float* out = (float*)d_out;
    k_all<<<GRID, NT, 12288>>>(in, out);
}